// round 16
// baseline (speedup 1.0000x reference)
#include <cuda_runtime.h>
#include <cuda_bf16.h>
#include <math.h>

#define Bn 4
#define Nn 4096
#define En 16384

#define ROWB 80                    // smem row stride bytes (64B data + 16B pad)
#define ASZ (256 * ROWB)           // A operand: 256 rows = 20480 B
#define BSZ (128 * ROWB)           // B operand: 128 rows = 10240 B
#define STGB (ASZ + BSZ)           // 30720 B per stage
#define SMEM_BYTES (2 * STGB)      // 61440 B
#define NCTA 148                   // persistent grid: one CTA per SM

// ---------------------------------------------------------------------------
// Static device scratch
// ---------------------------------------------------------------------------
__device__ __align__(16) float          g_AGd[2][(size_t)Bn * Nn * 512]; // double-buffered AG
__device__ __align__(16) float          g_Z  [(size_t)Bn * Nn * 256];
__device__ __align__(16) unsigned short g_rhb[(size_t)Bn * Nn * 256];
__device__ __align__(16) float          g_h  [(size_t)Bn * Nn * 256];
__device__ __align__(16) unsigned short g_hb [(size_t)Bn * Nn * 256];
__device__ __align__(16) float          g_ann[(size_t)Bn * Nn * 64];
__device__ __align__(16) unsigned short g_Wtb [16 * 256 * 256];
__device__ __align__(16) unsigned short g_Wrzb[512 * 768];
__device__ __align__(16) unsigned short g_Whb [256 * 768];
__device__ __align__(16) float g_brz[512];
__device__ __align__(16) float g_proj[16 * 50 * 256];
__device__ float g_nodeval[Bn * Nn];
__device__ int g_cnt[32], g_cur[32], g_off[33], g_toff[33];
__device__ int g_eidx[Bn * En];
__device__ int g_bar;          // monotonic grid barrier counter
__device__ int g_tc[8];        // per-phase work-steal counters

// ---------------------------------------------------------------------------
// Helpers
// ---------------------------------------------------------------------------
__device__ __forceinline__ unsigned pkbf(float lo, float hi) {
    unsigned r;
    asm("cvt.rn.bf16x2.f32 %0, %1, %2;" : "=r"(r) : "f"(hi), "f"(lo));
    return r;
}
__device__ __forceinline__ unsigned short f2b(float x) {
    __nv_bfloat16 b = __float2bfloat16(x);
    return *(unsigned short*)&b;
}
__device__ __forceinline__ float bfr(float x) {
    return __bfloat162float(__float2bfloat16(x));
}
__device__ __forceinline__ void redadd2(float* p, float x, float y) {
    asm volatile("red.global.add.v2.f32 [%0], {%1,%2};"
                 :: "l"(p), "f"(x), "f"(y) : "memory");
}
__device__ __forceinline__ void redadd4(float* p, float a, float b, float c, float d) {
    asm volatile("red.global.add.v4.f32 [%0], {%1,%2,%3,%4};"
                 :: "l"(p), "f"(a), "f"(b), "f"(c), "f"(d) : "memory");
}
__device__ __forceinline__ void mma_bf16(float* c, const unsigned* a, const unsigned* b) {
    asm volatile(
        "mma.sync.aligned.m16n8k16.row.col.f32.bf16.bf16.f32 "
        "{%0,%1,%2,%3}, {%4,%5,%6,%7}, {%8,%9}, {%0,%1,%2,%3};"
        : "+f"(c[0]), "+f"(c[1]), "+f"(c[2]), "+f"(c[3])
        : "r"(a[0]), "r"(a[1]), "r"(a[2]), "r"(a[3]), "r"(b[0]), "r"(b[1]));
}
__device__ __forceinline__ void ldmx4(unsigned& r0, unsigned& r1, unsigned& r2, unsigned& r3,
                                      unsigned addr) {
    asm volatile("ldmatrix.sync.aligned.m8n8.x4.shared.b16 {%0,%1,%2,%3}, [%4];"
                 : "=r"(r0), "=r"(r1), "=r"(r2), "=r"(r3) : "r"(addr));
}

// Consume one 256x128x32(bf16) stage: 16 warps (4m x 4n) of 64x32 tiles.
__device__ __forceinline__ void consume_stage(unsigned aBase, unsigned bBase,
                                              int wm, int wn, int lane,
                                              float acc[4][4][4])
{
    const unsigned aOff = aBase + (unsigned)(wm + (lane & 15)) * ROWB + (lane >> 4) * 16;
    const unsigned bOff = bBase +
        (unsigned)(wn + (lane & 7) + ((lane >> 4) & 1) * 8) * ROWB + ((lane >> 3) & 1) * 16;
#pragma unroll
    for (int ks = 0; ks < 2; ks++) {
        unsigned bf[4][2];
#pragma unroll
        for (int p = 0; p < 2; p++) {
            unsigned r0, r1, r2, r3;
            ldmx4(r0, r1, r2, r3, bOff + p * (16 * ROWB) + ks * 32);
            bf[2 * p][0] = r0;     bf[2 * p][1] = r1;
            bf[2 * p + 1][0] = r2; bf[2 * p + 1][1] = r3;
        }
#pragma unroll
        for (int mt = 0; mt < 4; mt++) {
            unsigned a[4];
            ldmx4(a[0], a[1], a[2], a[3], aOff + mt * (16 * ROWB) + ks * 32);
#pragma unroll
            for (int nt = 0; nt < 4; nt++)
                mma_bf16(acc[mt][nt], a, bf[nt]);
        }
    }
}

// ---------------------------------------------------------------------------
// Sort pipeline + setup + step-0 scatter (separate launches, unchanged logic)
// ---------------------------------------------------------------------------
__global__ void hist_k(const int* __restrict__ et) {
    __shared__ int h[32];
    int tid = threadIdx.x;
    if (tid < 32) h[tid] = 0;
    __syncthreads();
    int e = blockIdx.x * 256 + tid;
    atomicAdd(&h[(e >> 14) * 8 + et[e]], 1);
    __syncthreads();
    if (tid < 32 && h[tid] > 0) atomicAdd(&g_cnt[tid], h[tid]);
}

__global__ void scan_k() {
    int i = threadIdx.x;  // 32
    int c = g_cnt[i];
    int s = c, t = (c + 255) >> 8;
#pragma unroll
    for (int d = 1; d < 32; d <<= 1) {
        int u1 = __shfl_up_sync(0xffffffffu, s, d);
        int u2 = __shfl_up_sync(0xffffffffu, t, d);
        if (i >= d) { s += u1; t += u2; }
    }
    g_off[i + 1] = s;
    g_toff[i + 1] = t;
    g_cnt[i] = 0;              // reset for next replay
    g_cur[i] = 0;
    if (i < 8) g_tc[i] = 0;    // reset work-steal counters
    if (i == 0) { g_off[0] = 0; g_toff[0] = 0; g_bar = 0; }
}

__global__ void build_k(const int* __restrict__ et) {
    __shared__ int loc[32], base[32];
    int tid = threadIdx.x;
    if (tid < 32) loc[tid] = 0;
    __syncthreads();
    int e = blockIdx.x * 256 + tid;
    int bin = (e >> 14) * 8 + et[e];
    int rank = atomicAdd(&loc[bin], 1);
    __syncthreads();
    if (tid < 32 && loc[tid] > 0) base[tid] = atomicAdd(&g_cur[tid], loc[tid]);
    __syncthreads();
    g_eidx[g_off[bin] + base[bin] + rank] = e;
}

__global__ void setup_k(const int* __restrict__ ann_id, const float* __restrict__ te,
                        const float* __restrict__ ee,
                        const float* __restrict__ Wr, const float* __restrict__ Wz,
                        const float* __restrict__ br, const float* __restrict__ bz,
                        const float* __restrict__ Wh) {
    int bx = blockIdx.x, i = threadIdx.x;
    if (bx < 16384) {
        int id = ann_id[bx];
        float a = 0.f;
        if (i < 64 && id > 0) a = te[(size_t)(id - 1) * 64 + i];
        if (i < 64) g_ann[(size_t)bx * 64 + i] = a;
        float v = (i < 64) ? a : 0.f;
        g_h[(size_t)bx * 256 + i] = v;
        g_hb[(size_t)bx * 256 + i] = f2b(v);
        *(float2*)(g_AGd[0] + (size_t)bx * 512 + i * 2) = make_float2(0.f, 0.f);
    } else if (bx < 17408) {
        size_t q = ((size_t)(bx - 16384) * 256 + i) * 4;
        float4 v = *(const float4*)(ee + q);
        *(uint2*)(g_Wtb + q) = make_uint2(pkbf(v.x, v.y), pkbf(v.z, v.w));
    } else if (bx < 17920) {
        int r = bx - 17408;
        const float* s = (r < 256) ? (Wr + (size_t)r * 768) : (Wz + (size_t)(r - 256) * 768);
        for (int c = i; c < 768; c += 256)
            g_Wrzb[(size_t)r * 768 + c] = f2b(s[c]);
        if (i == 0) g_brz[r] = (r < 256) ? br[r] : bz[r - 256];
    } else if (bx < 18112) {
        size_t q = ((size_t)(bx - 17920) * 256 + i) * 4;
        float4 v = *(const float4*)(Wh + q);
        *(uint2*)(g_Whb + q) = make_uint2(pkbf(v.x, v.y), pkbf(v.z, v.w));
    } else {
        int p = bx - 18112;
        int t = p / 50, id = p % 50;
        int wid = i >> 5, lane = i & 31;
        float* outp = g_proj + ((size_t)t * 50 + id) * 256;
        if (id == 0) {
            if (wid == 0) {
                *(float4*)(outp + lane * 4) = make_float4(0.f, 0.f, 0.f, 0.f);
                *(float4*)(outp + 128 + lane * 4) = make_float4(0.f, 0.f, 0.f, 0.f);
            }
            return;
        }
        const float* tr = te + (size_t)(id - 1) * 64;
        float tlo = bfr(tr[lane]);
        float thi = bfr(tr[lane + 32]);
        for (int k = 0; k < 32; k++) {
            int row = wid * 32 + k;
            const float* wr = ee + (size_t)t * 65536 + (size_t)row * 256;
            float s = bfr(wr[lane]) * tlo + bfr(wr[lane + 32]) * thi;
#pragma unroll
            for (int o = 16; o; o >>= 1) s += __shfl_xor_sync(0xffffffffu, s, o);
            if (lane == 0) outp[row] = s;
        }
    }
}

__global__ void __launch_bounds__(256) scatter0_k(
    const int* __restrict__ src, const int* __restrict__ dst,
    const int* __restrict__ et, const int* __restrict__ ann_id,
    const float* __restrict__ eb)
{
    int e = blockIdx.x * 2 + (threadIdx.x >> 7);
    int tid2 = threadIdx.x & 127;
    int dir = tid2 >> 6, q = tid2 & 63;
    int b = e >> 14;
    int s = __ldg(&src[e]);
    int d = __ldg(&dst[e]);
    int t = __ldg(&et[e]);
    int gnode = dir ? s : d;
    int snode = dir ? d : s;
    int id = __ldg(&ann_id[b * Nn + gnode]);
    int tt = t + dir * 8;
    float4 v = ((const float4*)(g_proj + ((size_t)tt * 50 + id) * 256))[q];
    float4 bb = ((const float4*)(eb + (size_t)tt * 256))[q];
    float* tgt = g_AGd[0] + ((size_t)b * Nn + snode) * 512 + (dir ? 0 : 256) + q * 4;
    redadd4(tgt, v.x + bb.x, v.y + bb.y, v.z + bb.z, v.w + bb.w);
}

// ---------------------------------------------------------------------------
// Tile bodies (verbatim R15 logic, parametrized by tile coordinates)
// ---------------------------------------------------------------------------
__device__ void gather_tile(int tile, int n0, int dir, int pb,
                            const int* __restrict__ src, const int* __restrict__ dst,
                            const float* __restrict__ eb, char* sm, unsigned smB)
{
    int grp = 0;
#pragma unroll 1
    while (tile >= g_toff[grp + 1]) grp++;
    const int m0 = (tile - g_toff[grp]) * 256;
    const int off = g_off[grp];
    const int cnt = g_off[grp + 1] - off;
    const int b = grp >> 3, t = grp & 7;

    const int tid = threadIdx.x;
    const int lane = tid & 31, wid = tid >> 5;
    const int g = lane >> 2, tg = lane & 3;
    const int wm = (wid >> 2) * 64, wn = (wid & 3) * 32;

    const int* gidx = dir ? src : dst;
    const int* sidx = dir ? dst : src;
    const unsigned short* W = g_Wtb + (size_t)(t + dir * 8) * 65536;
    const float* bias = eb + (size_t)(t + dir * 8) * 256;
    float* agb = g_AGd[pb] + (size_t)b * Nn * 512 + (dir ? 0 : 256);

    const int arow = tid >> 1, ahalf = tid & 1;
    int mg = m0 + arow; if (mg >= cnt) mg = cnt - 1;
    const uint4* aRow = (const uint4*)(g_hb + ((size_t)b * Nn + gidx[g_eidx[off + mg]]) * 256);
    const int brow = tid >> 2, bq = tid & 3;
    const uint4* bRow = (const uint4*)(W + (size_t)(n0 + brow) * 256);
    const unsigned dA = (unsigned)arow * ROWB + ahalf * 32;
    const unsigned dB = ASZ + (unsigned)brow * ROWB + bq * 16;

    float acc[4][4][4];
#pragma unroll
    for (int mt = 0; mt < 4; mt++)
#pragma unroll
        for (int nt = 0; nt < 4; nt++)
#pragma unroll
            for (int c = 0; c < 4; c++) acc[mt][nt][c] = 0.f;

    uint4 va[2], vb;
    va[0] = aRow[ahalf * 2];
    va[1] = aRow[ahalf * 2 + 1];
    vb = bRow[bq];

    const int CH = 8;
    for (int c = 0; c < CH; c++) {
        char* sg = sm + (c & 1) * STGB;
        *(uint4*)(sg + dA) = va[0];
        *(uint4*)(sg + dA + 16) = va[1];
        *(uint4*)(sg + dB) = vb;
        if (c + 1 < CH) {
            va[0] = aRow[(c + 1) * 4 + ahalf * 2];
            va[1] = aRow[(c + 1) * 4 + ahalf * 2 + 1];
            vb = bRow[(c + 1) * 4 + bq];
        }
        __syncthreads();
        consume_stage(smB + (c & 1) * STGB, smB + (c & 1) * STGB + ASZ, wm, wn, lane, acc);
    }
    __syncthreads();

#pragma unroll
    for (int mt = 0; mt < 4; mt++) {
        int rA = m0 + wm + mt * 16 + g;
        int rB = rA + 8;
        bool vA = (rA < cnt), vB = (rB < cnt);
        float* pA = vA ? agb + (size_t)sidx[g_eidx[off + rA]] * 512 + n0 + wn + 2 * tg : nullptr;
        float* pB = vB ? agb + (size_t)sidx[g_eidx[off + rB]] * 512 + n0 + wn + 2 * tg : nullptr;
#pragma unroll
        for (int nt = 0; nt < 4; nt++) {
            int col = n0 + wn + nt * 8 + 2 * tg;
            float b0 = bias[col], b1 = bias[col + 1];
            if (vA) redadd2(pA + nt * 8, acc[mt][nt][0] + b0, acc[mt][nt][1] + b1);
            if (vB) redadd2(pB + nt * 8, acc[mt][nt][2] + b0, acc[mt][nt][3] + b1);
        }
    }
}

template <int ACT>
__device__ void gate_tile(int m0, int n0, int pb,
                          const unsigned short* __restrict__ A2,
                          const unsigned short* __restrict__ Bw,
                          const float* __restrict__ bias, int CH,
                          char* sm, unsigned smB)
{
    const int tid = threadIdx.x;
    const int lane = tid & 31, wid = tid >> 5;
    const int g = lane >> 2, tg = lane & 3;
    const int wm = (wid >> 2) * 64, wn = (wid & 3) * 32;

    const float* AG = g_AGd[pb];
    float* AGnext = g_AGd[pb ^ 1];

    const int arow = tid >> 1, ahalf = tid & 1;
    const float* agRow = AG + (size_t)(m0 + arow) * 512 + ahalf * 16;
    const uint4* a2Row = (const uint4*)(A2 + (size_t)(m0 + arow) * 256);
    const int brow = tid >> 2, bq = tid & 3;
    const uint4* bRow = (const uint4*)(Bw + (size_t)(n0 + brow) * 768);
    const unsigned dA = (unsigned)arow * ROWB + ahalf * 32;
    const unsigned dB = ASZ + (unsigned)brow * ROWB + bq * 16;

    float acc[4][4][4];
#pragma unroll
    for (int mt = 0; mt < 4; mt++)
#pragma unroll
        for (int nt = 0; nt < 4; nt++)
#pragma unroll
            for (int c = 0; c < 4; c++) acc[mt][nt][c] = 0.f;

    auto loadA = [&](int c, uint4* va) {
        if (c < 16) {
            const float4* p = (const float4*)(agRow + c * 32);
            float4 x0 = p[0], x1 = p[1], x2 = p[2], x3 = p[3];
            va[0] = make_uint4(pkbf(x0.x, x0.y), pkbf(x0.z, x0.w),
                               pkbf(x1.x, x1.y), pkbf(x1.z, x1.w));
            va[1] = make_uint4(pkbf(x2.x, x2.y), pkbf(x2.z, x2.w),
                               pkbf(x3.x, x3.y), pkbf(x3.z, x3.w));
        } else {
            va[0] = a2Row[(c - 16) * 4 + ahalf * 2];
            va[1] = a2Row[(c - 16) * 4 + ahalf * 2 + 1];
        }
    };

    uint4 va[2], vb;
    loadA(0, va);
    vb = bRow[bq];

    for (int c = 0; c < CH; c++) {
        char* sg = sm + (c & 1) * STGB;
        *(uint4*)(sg + dA) = va[0];
        *(uint4*)(sg + dA + 16) = va[1];
        *(uint4*)(sg + dB) = vb;
        if (c + 1 < CH) {
            loadA(c + 1, va);
            vb = bRow[(c + 1) * 4 + bq];
        }
        __syncthreads();
        consume_stage(smB + (c & 1) * STGB, smB + (c & 1) * STGB + ASZ, wm, wn, lane, acc);
    }
    __syncthreads();

#pragma unroll
    for (int mt = 0; mt < 4; mt++) {
#pragma unroll
        for (int half = 0; half < 2; half++) {
            int row = m0 + wm + mt * 16 + g + half * 8;
#pragma unroll
            for (int nt = 0; nt < 4; nt++) {
                int col = n0 + wn + nt * 8 + 2 * tg;
                float v0 = acc[mt][nt][half * 2] + bias[col];
                float v1 = acc[mt][nt][half * 2 + 1] + bias[col + 1];
                if (ACT == 1) {
                    float s0 = 1.f / (1.f + expf(-v0));
                    float s1 = 1.f / (1.f + expf(-v1));
                    if (col < 256) {
                        const float* hp = g_h + (size_t)row * 256 + col;
                        ((unsigned*)g_rhb)[((size_t)row * 256 + col) >> 1] =
                            pkbf(s0 * hp[0], s1 * hp[1]);
                    } else {
                        *(float2*)(g_Z + (size_t)row * 256 + (col - 256)) =
                            make_float2(s0, s1);
                    }
                } else {
                    float z0 = g_Z[(size_t)row * 256 + col];
                    float z1 = g_Z[(size_t)row * 256 + col + 1];
                    float* hp = g_h + (size_t)row * 256 + col;
                    float n0v = (1.f - z0) * hp[0] + z0 * tanhf(v0);
                    float n1v = (1.f - z1) * hp[1] + z1 * tanhf(v1);
                    *(float2*)hp = make_float2(n0v, n1v);
                    ((unsigned*)g_hb)[((size_t)row * 256 + col) >> 1] = pkbf(n0v, n1v);
                    float2 zz = make_float2(0.f, 0.f);
                    *(float2*)(AGnext + (size_t)row * 512 + col) = zz;
                    *(float2*)(AGnext + (size_t)row * 512 + col + 256) = zz;
                }
            }
        }
    }
}

// ---------------------------------------------------------------------------
// Persistent kernel: work-stealing phases + monotonic grid barriers
// ---------------------------------------------------------------------------
__global__ void __launch_bounds__(512, 1) persist_k(
    const int* __restrict__ src, const int* __restrict__ dst,
    const float* __restrict__ eb, const float* __restrict__ bh,
    const float* __restrict__ Wa, const float* __restrict__ ba,
    const float* __restrict__ Wo, const float* __restrict__ bo,
    float* __restrict__ out)
{
    extern __shared__ char sm[];
    unsigned smB;
    asm("{ .reg .u64 t; cvta.to.shared.u64 t, %1; cvt.u32.u64 %0, t; }"
        : "=r"(smB) : "l"(sm));
    const int tid = threadIdx.x;
    __shared__ int s_u;
    int epoch = 0;

    // grid barrier: monotonic epoch counter (reset by scan_k each replay)
    auto gbar = [&]() {
        __syncthreads();
        if (tid == 0) {
            __threadfence();
            atomicAdd(&g_bar, 1);
            epoch++;
            while (atomicAdd(&g_bar, 0) < epoch * NCTA) __nanosleep(64);
            __threadfence();
        }
        epoch = __shfl_sync(0xffffffffu, epoch, 0);  // keep lanes consistent (tid0's warp)
        __syncthreads();
    };
    // NOTE: epoch only matters in tid==0; shfl is a no-op safeguard.

    const int gcount = 4 * g_toff[32];   // gather work units: (tile, y, dir)

#pragma unroll 1
    for (int s = 0; s < 3; s++) {
        const int pb = s & 1;
        const int CH = (s == 0) ? 18 : 24;
        if (s > 0) {
            // gather phase (steal units)
            const int pc = 1 + (s - 1) * 3;  // phases 1, 4
            for (;;) {
                if (tid == 0) s_u = atomicAdd(&g_tc[pc], 1);
                __syncthreads();
                int u = s_u;
                if (u >= gcount) break;
                gather_tile(u >> 2, ((u >> 1) & 1) * 128, u & 1, pb, src, dst, eb, sm, smB);
                __syncthreads();
            }
            gbar();
        }
        // rz phase: 256 units (64 m x 4 n)
        {
            const int pc = (s == 0) ? 0 : (2 + (s - 1) * 3);  // phases 0, 2, 5
            for (;;) {
                if (tid == 0) s_u = atomicAdd(&g_tc[pc], 1);
                __syncthreads();
                int u = s_u;
                if (u >= 256) break;
                gate_tile<1>((u >> 2) * 256, (u & 3) * 128, pb, g_hb, g_Wrzb, g_brz,
                             CH, sm, smB);
                __syncthreads();
            }
            gbar();
        }
        // hh phase: 128 units (64 m x 2 n)
        {
            const int pc = (s == 0) ? 7 : (3 + (s - 1) * 3);  // phases 7, 3, 6
            for (;;) {
                if (tid == 0) s_u = atomicAdd(&g_tc[pc], 1);
                __syncthreads();
                int u = s_u;
                if (u >= 128) break;
                gate_tile<2>((u >> 1) * 256, (u & 1) * 128, pb, g_rhb, g_Whb, bh,
                             CH, sm, smB);
                __syncthreads();
            }
            gbar();
        }
    }

    // readout phase: grid-strided warps
    {
        const int lane = tid & 31;
        const int wtot = NCTA * 16;
        for (int node = blockIdx.x * 16 + (tid >> 5); node < Bn * Nn; node += wtot) {
            const float* hrow = g_h + (size_t)node * 256;
            const float* arow = g_ann + (size_t)node * 64;
            float sa = 0.f, so = 0.f;
#pragma unroll
            for (int k = lane; k < 320; k += 32) {
                float v = (k < 256) ? hrow[k] : arow[k - 256];
                sa += v * Wa[k];
                so += v * Wo[k];
            }
#pragma unroll
            for (int o = 16; o; o >>= 1) {
                sa += __shfl_xor_sync(0xffffffffu, sa, o);
                so += __shfl_xor_sync(0xffffffffu, so, o);
            }
            if (lane == 0) {
                float atten = 1.f / (1.f + expf(-(sa + ba[0])));
                float ou = tanhf(so + bo[0]);
                g_nodeval[node] = atten * ou;
            }
        }
    }
    gbar();

    // finalize: CTAs 0..3
    if (blockIdx.x < 4) {
        float* shf = (float*)sm;
        int b = blockIdx.x;
        float s = 0.f;
        for (int i = tid; i < Nn; i += 512) s += g_nodeval[(size_t)b * Nn + i];
        shf[tid] = s;
        __syncthreads();
        for (int k = 256; k; k >>= 1) {
            if (tid < k) shf[tid] += shf[tid + k];
            __syncthreads();
        }
        if (tid == 0) out[b] = 1.f / (1.f + expf(-shf[0]));
    }
}

// ---------------------------------------------------------------------------
// Launch: 6 launches total
// ---------------------------------------------------------------------------
extern "C" void kernel_launch(void* const* d_in, const int* in_sizes, int n_in,
                              void* d_out, int out_size) {
    (void)in_sizes; (void)n_in; (void)out_size;
    const int* ann_id = (const int*)d_in[0];
    const int* src    = (const int*)d_in[1];
    const int* dst    = (const int*)d_in[2];
    const int* et     = (const int*)d_in[3];
    const float* ee   = (const float*)d_in[4];
    const float* eb   = (const float*)d_in[5];
    const float* te   = (const float*)d_in[6];
    const float* Wr   = (const float*)d_in[7];
    const float* br   = (const float*)d_in[8];
    const float* Wz   = (const float*)d_in[9];
    const float* bz   = (const float*)d_in[10];
    const float* Wh   = (const float*)d_in[11];
    const float* bh   = (const float*)d_in[12];
    const float* Wa   = (const float*)d_in[13];
    const float* ba   = (const float*)d_in[14];
    const float* Wo   = (const float*)d_in[15];
    const float* bo   = (const float*)d_in[16];
    float* out = (float*)d_out;

    cudaFuncSetAttribute(persist_k, cudaFuncAttributeMaxDynamicSharedMemorySize, SMEM_BYTES);

    hist_k<<<256, 256>>>(et);
    scan_k<<<1, 32>>>();
    build_k<<<256, 256>>>(et);
    setup_k<<<18912, 256>>>(ann_id, te, ee, Wr, Wz, br, bz, Wh);
    scatter0_k<<<32768, 256>>>(src, dst, et, ann_id, eb);
    persist_k<<<NCTA, 512, SMEM_BYTES>>>(src, dst, eb, bh, Wa, ba, Wo, bo, out);
}

// round 17
// speedup vs baseline: 1.1718x; 1.1718x over previous
#include <cuda_runtime.h>
#include <cuda_bf16.h>
#include <math.h>

#define Bn 4
#define Nn 4096
#define En 16384

#define ROWB 80                    // smem row stride bytes (64B data + 16B pad)
#define ASZ (256 * ROWB)           // A operand: 256 rows = 20480 B
#define BSZ (128 * ROWB)           // B operand: 128 rows = 10240 B
#define STGB (ASZ + BSZ)           // 30720 B per stage
#define SMEM_BYTES (2 * STGB)      // 61440 B

// ---------------------------------------------------------------------------
// Static device scratch
// ---------------------------------------------------------------------------
__device__ __align__(16) float          g_AGd[2][(size_t)Bn * Nn * 512]; // double-buffered AG
__device__ __align__(16) float          g_Z  [(size_t)Bn * Nn * 256];  // z fp32
__device__ __align__(16) unsigned short g_rhb[(size_t)Bn * Nn * 256];  // r*h bf16
__device__ __align__(16) float          g_h  [(size_t)Bn * Nn * 256];  // state fp32
__device__ __align__(16) unsigned short g_hb [(size_t)Bn * Nn * 256];  // state bf16
__device__ __align__(16) float          g_ann[(size_t)Bn * Nn * 64];
__device__ __align__(16) unsigned short g_Wtb [16 * 256 * 256];
__device__ __align__(16) unsigned short g_Wrzb[512 * 768];
__device__ __align__(16) unsigned short g_Whb [256 * 768];
__device__ __align__(16) float g_brz[512];
__device__ __align__(16) float g_proj[16 * 50 * 256];  // step-0 msg table [t][ann][i]
__device__ float g_nodeval[Bn * Nn];
__device__ int g_cnt[32], g_cur[32], g_off[33], g_toff[33];
__device__ int g_eidx[Bn * En];

// ---------------------------------------------------------------------------
// Helpers
// ---------------------------------------------------------------------------
__device__ __forceinline__ unsigned pkbf(float lo, float hi) {
    unsigned r;
    asm("cvt.rn.bf16x2.f32 %0, %1, %2;" : "=r"(r) : "f"(hi), "f"(lo));
    return r;
}
__device__ __forceinline__ unsigned short f2b(float x) {
    __nv_bfloat16 b = __float2bfloat16(x);
    return *(unsigned short*)&b;
}
__device__ __forceinline__ float bfr(float x) {
    return __bfloat162float(__float2bfloat16(x));
}
__device__ __forceinline__ unsigned smaddr(const void* p) {
    unsigned a;
    asm("{ .reg .u64 t; cvta.to.shared.u64 t, %1; cvt.u32.u64 %0, t; }"
        : "=r"(a) : "l"(p));
    return a;
}
__device__ __forceinline__ void redadd2(float* p, float x, float y) {
    asm volatile("red.global.add.v2.f32 [%0], {%1,%2};"
                 :: "l"(p), "f"(x), "f"(y) : "memory");
}
__device__ __forceinline__ void redadd4(float* p, float a, float b, float c, float d) {
    asm volatile("red.global.add.v4.f32 [%0], {%1,%2,%3,%4};"
                 :: "l"(p), "f"(a), "f"(b), "f"(c), "f"(d) : "memory");
}
__device__ __forceinline__ void mma_bf16(float* c, const unsigned* a, const unsigned* b) {
    asm volatile(
        "mma.sync.aligned.m16n8k16.row.col.f32.bf16.bf16.f32 "
        "{%0,%1,%2,%3}, {%4,%5,%6,%7}, {%8,%9}, {%0,%1,%2,%3};"
        : "+f"(c[0]), "+f"(c[1]), "+f"(c[2]), "+f"(c[3])
        : "r"(a[0]), "r"(a[1]), "r"(a[2]), "r"(a[3]), "r"(b[0]), "r"(b[1]));
}
__device__ __forceinline__ void ldmx4(unsigned& r0, unsigned& r1, unsigned& r2, unsigned& r3,
                                      unsigned addr) {
    asm volatile("ldmatrix.sync.aligned.m8n8.x4.shared.b16 {%0,%1,%2,%3}, [%4];"
                 : "=r"(r0), "=r"(r1), "=r"(r2), "=r"(r3) : "r"(addr));
}

// Consume one 256x128x32(bf16) stage: 16 warps (4m x 4n) of 64x32 tiles.
__device__ __forceinline__ void consume_stage(unsigned aBase, unsigned bBase,
                                              int wm, int wn, int lane,
                                              float acc[4][4][4])
{
    const unsigned aOff = aBase + (unsigned)(wm + (lane & 15)) * ROWB + (lane >> 4) * 16;
    const unsigned bOff = bBase +
        (unsigned)(wn + (lane & 7) + ((lane >> 4) & 1) * 8) * ROWB + ((lane >> 3) & 1) * 16;
#pragma unroll
    for (int ks = 0; ks < 2; ks++) {
        unsigned bf[4][2];
#pragma unroll
        for (int p = 0; p < 2; p++) {
            unsigned r0, r1, r2, r3;
            ldmx4(r0, r1, r2, r3, bOff + p * (16 * ROWB) + ks * 32);
            bf[2 * p][0] = r0;     bf[2 * p][1] = r1;
            bf[2 * p + 1][0] = r2; bf[2 * p + 1][1] = r3;
        }
#pragma unroll
        for (int mt = 0; mt < 4; mt++) {
            unsigned a[4];
            ldmx4(a[0], a[1], a[2], a[3], aOff + mt * (16 * ROWB) + ks * 32);
#pragma unroll
            for (int nt = 0; nt < 4; nt++)
                mma_bf16(acc[mt][nt], a, bf[nt]);
        }
    }
}

// ---------------------------------------------------------------------------
// Sort pipeline: hist (multi-CTA) -> scan (resets cnt/cur for next replay) -> build
// ---------------------------------------------------------------------------
__global__ void hist_k(const int* __restrict__ et) {
    __shared__ int h[32];
    int tid = threadIdx.x;
    if (tid < 32) h[tid] = 0;
    __syncthreads();
    int e = blockIdx.x * 256 + tid;
    atomicAdd(&h[(e >> 14) * 8 + et[e]], 1);
    __syncthreads();
    if (tid < 32 && h[tid] > 0) atomicAdd(&g_cnt[tid], h[tid]);
}

__global__ void scan_k() {
    int i = threadIdx.x;  // 32
    int c = g_cnt[i];
    int s = c, t = (c + 255) >> 8;
#pragma unroll
    for (int d = 1; d < 32; d <<= 1) {
        int u1 = __shfl_up_sync(0xffffffffu, s, d);
        int u2 = __shfl_up_sync(0xffffffffu, t, d);
        if (i >= d) { s += u1; t += u2; }
    }
    g_off[i + 1] = s;
    g_toff[i + 1] = t;
    g_cnt[i] = 0;          // reset for next graph replay
    g_cur[i] = 0;
    if (i == 0) { g_off[0] = 0; g_toff[0] = 0; }
}

__global__ void build_k(const int* __restrict__ et) {
    __shared__ int loc[32], base[32];
    int tid = threadIdx.x;
    if (tid < 32) loc[tid] = 0;
    __syncthreads();
    int e = blockIdx.x * 256 + tid;
    int bin = (e >> 14) * 8 + et[e];
    int rank = atomicAdd(&loc[bin], 1);
    __syncthreads();
    if (tid < 32 && loc[tid] > 0) base[tid] = atomicAdd(&g_cur[tid], loc[tid]);
    __syncthreads();
    g_eidx[g_off[bin] + base[bin] + rank] = e;
}

// ---------------------------------------------------------------------------
// Fused setup: [warp-per-node init | Wt x4 | Wrz | Wh x4 | proj warp-ladder]
// grid 4576 = 2048 + 1024 + 512 + 192 + 800
// ---------------------------------------------------------------------------
__global__ void setup_k(const int* __restrict__ ann_id, const float* __restrict__ te,
                        const float* __restrict__ ee,
                        const float* __restrict__ Wr, const float* __restrict__ Wz,
                        const float* __restrict__ br, const float* __restrict__ bz,
                        const float* __restrict__ Wh) {
    int bx = blockIdx.x, i = threadIdx.x;
    if (bx < 2048) {
        // warp per node: vectorized init of ann / h / hb / AG[0]
        int node = bx * 8 + (i >> 5);
        int lane = i & 31;
        int id = __ldg(&ann_id[node]);
        float4 hv = make_float4(0.f, 0.f, 0.f, 0.f);
        if (lane < 16 && id > 0)
            hv = ((const float4*)(te + (size_t)(id - 1) * 64))[lane];
        float4 zz = make_float4(0.f, 0.f, 0.f, 0.f);
        float4* h4 = (float4*)(g_h + (size_t)node * 256);
        uint2* hb2 = (uint2*)(g_hb + (size_t)node * 256);
        uint2 hpk = make_uint2(pkbf(hv.x, hv.y), pkbf(hv.z, hv.w));
        h4[lane] = (lane < 16) ? hv : zz;        // floats 0..127
        h4[32 + lane] = zz;                      // floats 128..255
        hb2[lane] = (lane < 16) ? hpk : make_uint2(0u, 0u);
        hb2[32 + lane] = make_uint2(0u, 0u);
        if (lane < 16) ((float4*)(g_ann + (size_t)node * 64))[lane] = hv;
        float4* ag4 = (float4*)(g_AGd[0] + (size_t)node * 512);
#pragma unroll
        for (int k = 0; k < 4; k++) ag4[lane + k * 32] = zz;
    } else if (bx < 3072) {            // Wt: 1024 blocks x 256 thr x 4 elems
        size_t q = ((size_t)(bx - 2048) * 256 + i) * 4;
        float4 v = *(const float4*)(ee + q);
        *(uint2*)(g_Wtb + q) = make_uint2(pkbf(v.x, v.y), pkbf(v.z, v.w));
    } else if (bx < 3584) {            // Wrz: 512 rows
        int r = bx - 3072;
        const float* s = (r < 256) ? (Wr + (size_t)r * 768) : (Wz + (size_t)(r - 256) * 768);
        for (int c = i; c < 768; c += 256)
            g_Wrzb[(size_t)r * 768 + c] = f2b(s[c]);
        if (i == 0) g_brz[r] = (r < 256) ? br[r] : bz[r - 256];
    } else if (bx < 3776) {            // Wh: 192 blocks x 256 thr x 4 elems
        size_t q = ((size_t)(bx - 3584) * 256 + i) * 4;
        float4 v = *(const float4*)(Wh + q);
        *(uint2*)(g_Whb + q) = make_uint2(pkbf(v.x, v.y), pkbf(v.z, v.w));
    } else {                           // proj: 800 blocks = (t, ann id), warp-ladder
        int p = bx - 3776;
        int t = p / 50, id = p % 50;
        int wid = i >> 5, lane = i & 31;
        float* outp = g_proj + ((size_t)t * 50 + id) * 256;
        if (id == 0) {
            if (wid == 0) {
                *(float4*)(outp + lane * 4) = make_float4(0.f, 0.f, 0.f, 0.f);
                *(float4*)(outp + 128 + lane * 4) = make_float4(0.f, 0.f, 0.f, 0.f);
            }
            return;
        }
        const float* tr = te + (size_t)(id - 1) * 64;
        float tlo = bfr(tr[lane]);
        float thi = bfr(tr[lane + 32]);
        for (int k = 0; k < 32; k++) {
            int row = wid * 32 + k;
            const float* wr = ee + (size_t)t * 65536 + (size_t)row * 256;
            float s = bfr(wr[lane]) * tlo + bfr(wr[lane + 32]) * thi;
#pragma unroll
            for (int o = 16; o; o >>= 1) s += __shfl_xor_sync(0xffffffffu, s, o);
            if (lane == 0) outp[row] = s;
        }
    }
}

// ---------------------------------------------------------------------------
// Step-0 edge scatter: message = proj[t][ann(gathered)] + eb[t] (no GEMM).
// ---------------------------------------------------------------------------
__global__ void __launch_bounds__(256) scatter0_k(
    const int* __restrict__ src, const int* __restrict__ dst,
    const int* __restrict__ et, const int* __restrict__ ann_id,
    const float* __restrict__ eb)
{
    int e = blockIdx.x * 2 + (threadIdx.x >> 7);
    int tid2 = threadIdx.x & 127;
    int dir = tid2 >> 6, q = tid2 & 63;
    int b = e >> 14;
    int s = __ldg(&src[e]);
    int d = __ldg(&dst[e]);
    int t = __ldg(&et[e]);
    int gnode = dir ? s : d;
    int snode = dir ? d : s;
    int id = __ldg(&ann_id[b * Nn + gnode]);
    int tt = t + dir * 8;
    float4 v = ((const float4*)(g_proj + ((size_t)tt * 50 + id) * 256))[q];
    float4 bb = ((const float4*)(eb + (size_t)tt * 256))[q];
    float* tgt = g_AGd[0] + ((size_t)b * Nn + snode) * 512 + (dir ? 0 : 256) + q * 4;
    redadd4(tgt, v.x + bb.x, v.y + bb.y, v.z + bb.z, v.w + bb.w);
}

// ---------------------------------------------------------------------------
// Gather-GEMM + fused scatter (steps 1,2). grid (288, 2, 2).
// ---------------------------------------------------------------------------
__global__ void __launch_bounds__(512, 1) gather_k(
    int pb, const int* __restrict__ src, const int* __restrict__ dst,
    const float* __restrict__ eb)
{
    int tile = blockIdx.x;
    if (tile >= g_toff[32]) return;
    int grp = 0;
#pragma unroll 1
    while (tile >= g_toff[grp + 1]) grp++;
    const int m0 = (tile - g_toff[grp]) * 256;
    const int off = g_off[grp];
    const int cnt = g_off[grp + 1] - off;
    const int dir = blockIdx.z;
    const int b = grp >> 3, t = grp & 7;
    const int n0 = blockIdx.y * 128;

    extern __shared__ char sm[];
    const unsigned smB = smaddr(sm);

    const int tid = threadIdx.x;
    const int lane = tid & 31, wid = tid >> 5;
    const int g = lane >> 2, tg = lane & 3;
    const int wm = (wid >> 2) * 64, wn = (wid & 3) * 32;

    const int* gidx = dir ? src : dst;
    const int* sidx = dir ? dst : src;
    const unsigned short* W = g_Wtb + (size_t)(t + dir * 8) * 65536;
    const float* bias = eb + (size_t)(t + dir * 8) * 256;
    float* agb = g_AGd[pb] + (size_t)b * Nn * 512 + (dir ? 0 : 256);

    const int arow = tid >> 1, ahalf = tid & 1;
    int mg = m0 + arow; if (mg >= cnt) mg = cnt - 1;
    const uint4* aRow = (const uint4*)(g_hb + ((size_t)b * Nn + gidx[g_eidx[off + mg]]) * 256);
    const int brow = tid >> 2, bq = tid & 3;
    const uint4* bRow = (const uint4*)(W + (size_t)(n0 + brow) * 256);
    const unsigned dA = (unsigned)arow * ROWB + ahalf * 32;
    const unsigned dB = ASZ + (unsigned)brow * ROWB + bq * 16;

    float acc[4][4][4];
#pragma unroll
    for (int mt = 0; mt < 4; mt++)
#pragma unroll
        for (int nt = 0; nt < 4; nt++)
#pragma unroll
            for (int c = 0; c < 4; c++) acc[mt][nt][c] = 0.f;

    uint4 va[2], vb;
    va[0] = aRow[ahalf * 2];
    va[1] = aRow[ahalf * 2 + 1];
    vb = bRow[bq];

    const int CH = 8;
    for (int c = 0; c < CH; c++) {
        char* sg = sm + (c & 1) * STGB;
        *(uint4*)(sg + dA) = va[0];
        *(uint4*)(sg + dA + 16) = va[1];
        *(uint4*)(sg + dB) = vb;
        if (c + 1 < CH) {
            va[0] = aRow[(c + 1) * 4 + ahalf * 2];
            va[1] = aRow[(c + 1) * 4 + ahalf * 2 + 1];
            vb = bRow[(c + 1) * 4 + bq];
        }
        __syncthreads();
        consume_stage(smB + (c & 1) * STGB, smB + (c & 1) * STGB + ASZ, wm, wn, lane, acc);
    }

#pragma unroll
    for (int mt = 0; mt < 4; mt++) {
        int rA = m0 + wm + mt * 16 + g;
        int rB = rA + 8;
        bool vA = (rA < cnt), vB = (rB < cnt);
        float* pA = vA ? agb + (size_t)sidx[g_eidx[off + rA]] * 512 + n0 + wn + 2 * tg : nullptr;
        float* pB = vB ? agb + (size_t)sidx[g_eidx[off + rB]] * 512 + n0 + wn + 2 * tg : nullptr;
#pragma unroll
        for (int nt = 0; nt < 4; nt++) {
            int col = n0 + wn + nt * 8 + 2 * tg;
            float b0 = bias[col], b1 = bias[col + 1];
            if (vA) redadd2(pA + nt * 8, acc[mt][nt][0] + b0, acc[mt][nt][1] + b1);
            if (vB) redadd2(pB + nt * 8, acc[mt][nt][2] + b0, acc[mt][nt][3] + b1);
        }
    }
}

// ---------------------------------------------------------------------------
// Gate GEMMs over all batches. ACT 1 = rz, ACT 2 = hh (+ zero AG[next buffer]).
// ---------------------------------------------------------------------------
template <int ACT>
__device__ __forceinline__ void gate_core(int pb,
                                          const unsigned short* __restrict__ A2,
                                          const unsigned short* __restrict__ Bw,
                                          const float* __restrict__ bias, int CH)
{
    extern __shared__ char sm[];
    const unsigned smB = smaddr(sm);

    const int tid = threadIdx.x;
    const int lane = tid & 31, wid = tid >> 5;
    const int g = lane >> 2, tg = lane & 3;
    const int wm = (wid >> 2) * 64, wn = (wid & 3) * 32;
    const int m0 = blockIdx.x * 256;
    const int n0 = blockIdx.y * 128;

    const float* AG = g_AGd[pb];
    float* AGnext = g_AGd[pb ^ 1];

    const int arow = tid >> 1, ahalf = tid & 1;
    const float* agRow = AG + (size_t)(m0 + arow) * 512 + ahalf * 16;
    const uint4* a2Row = (const uint4*)(A2 + (size_t)(m0 + arow) * 256);
    const int brow = tid >> 2, bq = tid & 3;
    const uint4* bRow = (const uint4*)(Bw + (size_t)(n0 + brow) * 768);
    const unsigned dA = (unsigned)arow * ROWB + ahalf * 32;
    const unsigned dB = ASZ + (unsigned)brow * ROWB + bq * 16;

    float acc[4][4][4];
#pragma unroll
    for (int mt = 0; mt < 4; mt++)
#pragma unroll
        for (int nt = 0; nt < 4; nt++)
#pragma unroll
            for (int c = 0; c < 4; c++) acc[mt][nt][c] = 0.f;

    auto loadA = [&](int c, uint4* va) {
        if (c < 16) {
            const float4* p = (const float4*)(agRow + c * 32);
            float4 x0 = p[0], x1 = p[1], x2 = p[2], x3 = p[3];
            va[0] = make_uint4(pkbf(x0.x, x0.y), pkbf(x0.z, x0.w),
                               pkbf(x1.x, x1.y), pkbf(x1.z, x1.w));
            va[1] = make_uint4(pkbf(x2.x, x2.y), pkbf(x2.z, x2.w),
                               pkbf(x3.x, x3.y), pkbf(x3.z, x3.w));
        } else {
            va[0] = a2Row[(c - 16) * 4 + ahalf * 2];
            va[1] = a2Row[(c - 16) * 4 + ahalf * 2 + 1];
        }
    };

    uint4 va[2], vb;
    loadA(0, va);
    vb = bRow[bq];

    for (int c = 0; c < CH; c++) {
        char* sg = sm + (c & 1) * STGB;
        *(uint4*)(sg + dA) = va[0];
        *(uint4*)(sg + dA + 16) = va[1];
        *(uint4*)(sg + dB) = vb;
        if (c + 1 < CH) {
            loadA(c + 1, va);
            vb = bRow[(c + 1) * 4 + bq];
        }
        __syncthreads();
        consume_stage(smB + (c & 1) * STGB, smB + (c & 1) * STGB + ASZ, wm, wn, lane, acc);
    }

#pragma unroll
    for (int mt = 0; mt < 4; mt++) {
#pragma unroll
        for (int half = 0; half < 2; half++) {
            int row = m0 + wm + mt * 16 + g + half * 8;
#pragma unroll
            for (int nt = 0; nt < 4; nt++) {
                int col = n0 + wn + nt * 8 + 2 * tg;
                float v0 = acc[mt][nt][half * 2] + bias[col];
                float v1 = acc[mt][nt][half * 2 + 1] + bias[col + 1];
                if (ACT == 1) {
                    float s0 = 1.f / (1.f + expf(-v0));
                    float s1 = 1.f / (1.f + expf(-v1));
                    if (col < 256) {
                        const float* hp = g_h + (size_t)row * 256 + col;
                        ((unsigned*)g_rhb)[((size_t)row * 256 + col) >> 1] =
                            pkbf(s0 * hp[0], s1 * hp[1]);
                    } else {
                        *(float2*)(g_Z + (size_t)row * 256 + (col - 256)) =
                            make_float2(s0, s1);
                    }
                } else {
                    float z0 = g_Z[(size_t)row * 256 + col];
                    float z1 = g_Z[(size_t)row * 256 + col + 1];
                    float* hp = g_h + (size_t)row * 256 + col;
                    float n0v = (1.f - z0) * hp[0] + z0 * tanhf(v0);
                    float n1v = (1.f - z1) * hp[1] + z1 * tanhf(v1);
                    *(float2*)hp = make_float2(n0v, n1v);
                    ((unsigned*)g_hb)[((size_t)row * 256 + col) >> 1] = pkbf(n0v, n1v);
                    // fused zero of NEXT step's AG buffer (distinct memory, no race)
                    float2 zz = make_float2(0.f, 0.f);
                    *(float2*)(AGnext + (size_t)row * 512 + col) = zz;
                    *(float2*)(AGnext + (size_t)row * 512 + col + 256) = zz;
                }
            }
        }
    }
}

__global__ void __launch_bounds__(512, 1) rz_k(int pb, int CH) {
    gate_core<1>(pb, g_hb, g_Wrzb, g_brz, CH);
}
__global__ void __launch_bounds__(512, 1) hh_k(int pb, const float* __restrict__ bh, int CH) {
    gate_core<2>(pb, g_rhb, g_Whb, bh, CH);
}

// ---------------------------------------------------------------------------
// Readout + finalize
// ---------------------------------------------------------------------------
__global__ void readout_k(const float* __restrict__ Wa, const float* __restrict__ ba,
                          const float* __restrict__ Wo, const float* __restrict__ bo) {
    int node = (blockIdx.x * blockDim.x + threadIdx.x) >> 5;
    int lane = threadIdx.x & 31;
    const float* hrow = g_h + (size_t)node * 256;
    const float* arow = g_ann + (size_t)node * 64;
    float sa = 0.f, so = 0.f;
#pragma unroll
    for (int k = lane; k < 320; k += 32) {
        float v = (k < 256) ? hrow[k] : arow[k - 256];
        sa += v * Wa[k];
        so += v * Wo[k];
    }
#pragma unroll
    for (int off = 16; off; off >>= 1) {
        sa += __shfl_xor_sync(0xffffffffu, sa, off);
        so += __shfl_xor_sync(0xffffffffu, so, off);
    }
    if (lane == 0) {
        float atten = 1.f / (1.f + expf(-(sa + ba[0])));
        float ou = tanhf(so + bo[0]);
        g_nodeval[node] = atten * ou;
    }
}
__global__ void finalize_k(float* __restrict__ out) {
    __shared__ float sh[256];
    int b = blockIdx.x;
    float s = 0.f;
    for (int i = threadIdx.x; i < Nn; i += 256) s += g_nodeval[(size_t)b * Nn + i];
    sh[threadIdx.x] = s;
    __syncthreads();
    for (int k = 128; k; k >>= 1) {
        if (threadIdx.x < k) sh[threadIdx.x] += sh[threadIdx.x + k];
        __syncthreads();
    }
    if (threadIdx.x == 0) out[b] = 1.f / (1.f + expf(-sh[0]));
}

// ---------------------------------------------------------------------------
// Launch: single stream, 15 launches
// ---------------------------------------------------------------------------
extern "C" void kernel_launch(void* const* d_in, const int* in_sizes, int n_in,
                              void* d_out, int out_size) {
    (void)in_sizes; (void)n_in; (void)out_size;
    const int* ann_id = (const int*)d_in[0];
    const int* src    = (const int*)d_in[1];
    const int* dst    = (const int*)d_in[2];
    const int* et     = (const int*)d_in[3];
    const float* ee   = (const float*)d_in[4];
    const float* eb   = (const float*)d_in[5];
    const float* te   = (const float*)d_in[6];
    const float* Wr   = (const float*)d_in[7];
    const float* br   = (const float*)d_in[8];
    const float* Wz   = (const float*)d_in[9];
    const float* bz   = (const float*)d_in[10];
    const float* Wh   = (const float*)d_in[11];
    const float* bh   = (const float*)d_in[12];
    const float* Wa   = (const float*)d_in[13];
    const float* ba   = (const float*)d_in[14];
    const float* Wo   = (const float*)d_in[15];
    const float* bo   = (const float*)d_in[16];
    float* out = (float*)d_out;

    cudaFuncSetAttribute(gather_k, cudaFuncAttributeMaxDynamicSharedMemorySize, SMEM_BYTES);
    cudaFuncSetAttribute(rz_k, cudaFuncAttributeMaxDynamicSharedMemorySize, SMEM_BYTES);
    cudaFuncSetAttribute(hh_k, cudaFuncAttributeMaxDynamicSharedMemorySize, SMEM_BYTES);

    hist_k<<<256, 256>>>(et);
    scan_k<<<1, 32>>>();
    build_k<<<256, 256>>>(et);
    setup_k<<<4576, 256>>>(ann_id, te, ee, Wr, Wz, br, bz, Wh);

    for (int s = 0; s < 3; s++) {
        int pb = s & 1;   // AG buffer parity: step 0 -> buf0, 1 -> buf1, 2 -> buf0
        if (s == 0) {
            scatter0_k<<<32768, 256>>>(src, dst, et, ann_id, eb);
        } else {
            gather_k<<<dim3(288, 2, 2), 512, SMEM_BYTES>>>(pb, src, dst, eb);
        }
        rz_k<<<dim3(64, 4, 1), 512, SMEM_BYTES>>>(pb, s == 0 ? 18 : 24);
        hh_k<<<dim3(64, 2, 1), 512, SMEM_BYTES>>>(pb, bh, s == 0 ? 18 : 24);
    }

    readout_k<<<2048, 256>>>(Wa, ba, Wo, bo);
    finalize_k<<<4, 256>>>(out);
}